// round 9
// baseline (speedup 1.0000x reference)
#include <cuda_runtime.h>
#include <cstdint>

// LIF timestep, elementwise over N = 16*56*56*256 = 12,845,056 elements.
// Inputs: impulse, mem, mem_acc, refrac_until, spikecounts (float32 each)
// Output: 6 stacked planes [spikes, mem, mem_acc, refrac, counts, spiketrain]
//
// R9: 256-bit LOADS using the ptxas-sanctioned sm_103a encoding
// (ld.global.nc.L2::evict_last.v8.b32 — the exact form the R5 error message
// named as legal). Stores remain proven 128-bit float4. One 8-float tile
// per thread, exact grid (6272 blocks x 256 thr, no tail). R8's bare
// v8.b32 forms failed the container; this is the minimal-risk retry.

#define V_THRESH 1.0f
#define TIME_C 0.5f
#define REFRAC_SET 2.5f   // TIME + TAU_REFRAC

__device__ __forceinline__ void ldg256(const float* p, float* r) {
    uint32_t a0, a1, a2, a3, a4, a5, a6, a7;
    asm("ld.global.nc.L2::evict_last.v8.b32 {%0,%1,%2,%3,%4,%5,%6,%7}, [%8];"
        : "=r"(a0), "=r"(a1), "=r"(a2), "=r"(a3),
          "=r"(a4), "=r"(a5), "=r"(a6), "=r"(a7)
        : "l"(p));
    r[0] = __uint_as_float(a0); r[1] = __uint_as_float(a1);
    r[2] = __uint_as_float(a2); r[3] = __uint_as_float(a3);
    r[4] = __uint_as_float(a4); r[5] = __uint_as_float(a5);
    r[6] = __uint_as_float(a6); r[7] = __uint_as_float(a7);
}

__global__ void __launch_bounds__(256)
spike_layer_kernel(const float* __restrict__ impulse,
                   const float* __restrict__ mem,
                   const float* __restrict__ mem_acc,
                   const float* __restrict__ refrac_until,
                   const float* __restrict__ spikecounts,
                   float* __restrict__ out,   // 6 planes of n floats each
                   int n8) {                  // number of 8-float tiles
    const int t = blockIdx.x * blockDim.x + threadIdx.x;
    if (t >= n8) return;
    const size_t base = (size_t)t * 8;        // 32B-aligned
    const size_t n = (size_t)n8 * 8;

    // Front-batch all 5 wide loads (5 LDG.256 in flight = 160B/thread)
    float imp[8], m[8], ma[8], ru[8], sc[8];
    ldg256(impulse + base, imp);
    ldg256(mem + base, m);
    ldg256(mem_acc + base, ma);
    ldg256(refrac_until + base, ru);
    ldg256(spikecounts + base, sc);

    float o_spk[8], o_mem[8], o_acc[8], o_ref[8], o_cnt[8], o_trn[8];

    #pragma unroll
    for (int l = 0; l < 8; ++l) {
        // refractory mask on input
        const float masked  = (ru[l] > TIME_C) ? 0.0f : imp[l];
        const float new_mem = m[l] + masked;
        const float new_acc = ma[l] + masked;

        // linear activation: spikes in {0, V_THRESH}
        const bool  fired  = (new_mem >= V_THRESH);
        const float spikes = fired ? V_THRESH : 0.0f;

        // reset by subtraction (spikes<0 branch unreachable: spikes>=0)
        o_spk[l] = spikes;
        o_mem[l] = fired ? (new_mem - V_THRESH) : new_mem;
        o_acc[l] = new_acc;
        o_ref[l] = fired ? REFRAC_SET : ru[l];
        o_cnt[l] = sc[l] + (fired ? 1.0f : 0.0f);
        o_trn[l] = spikes * TIME_C;
    }

    // Stores: proven 128-bit float4 path (2 per plane)
    #pragma unroll
    for (int h = 0; h < 2; ++h) {
        const int o = h * 4;
        *(float4*)(out + 0 * n + base + o) = make_float4(o_spk[o], o_spk[o+1], o_spk[o+2], o_spk[o+3]);
        *(float4*)(out + 1 * n + base + o) = make_float4(o_mem[o], o_mem[o+1], o_mem[o+2], o_mem[o+3]);
        *(float4*)(out + 2 * n + base + o) = make_float4(o_acc[o], o_acc[o+1], o_acc[o+2], o_acc[o+3]);
        *(float4*)(out + 3 * n + base + o) = make_float4(o_ref[o], o_ref[o+1], o_ref[o+2], o_ref[o+3]);
        *(float4*)(out + 4 * n + base + o) = make_float4(o_cnt[o], o_cnt[o+1], o_cnt[o+2], o_cnt[o+3]);
        *(float4*)(out + 5 * n + base + o) = make_float4(o_trn[o], o_trn[o+1], o_trn[o+2], o_trn[o+3]);
    }
}

extern "C" void kernel_launch(void* const* d_in, const int* in_sizes, int n_in,
                              void* d_out, int out_size) {
    const float* impulse      = (const float*)d_in[0];
    const float* mem          = (const float*)d_in[1];
    const float* mem_acc      = (const float*)d_in[2];
    const float* refrac_until = (const float*)d_in[3];
    const float* spikecounts  = (const float*)d_in[4];
    float* out = (float*)d_out;

    const int n  = in_sizes[0];       // 12,845,056 (divisible by 8)
    const int n8 = n / 8;             // 1,605,632

    const int threads = 256;
    const int blocks  = (n8 + threads - 1) / threads;   // 6272 exact
    spike_layer_kernel<<<blocks, threads>>>(impulse, mem, mem_acc,
                                            refrac_until, spikecounts,
                                            out, n8);
}

// round 10
// speedup vs baseline: 1.4261x; 1.4261x over previous
#include <cuda_runtime.h>

// LIF timestep, elementwise over N = 16*56*56*256 = 12,845,056 elements.
// Inputs (metadata order): impulse, mem, mem_acc, refrac_until, spikecounts
// Output: 6 stacked planes of N floats:
//   [spikes, mem_out, mem_acc_out, refrac_out, counts_out, spiketrain]
//
// FINAL (= R1): float4 vectorization, one tile per thread, all 5 loads
// front-batched (MLP=5), exact grid. Measured 79.6us kernel, 6398 GB/s =
// 80% of HBM spec — the LTS/bus-turnaround ceiling for this 45R/55W mix.
// Refuted alternatives: ILP=2 capped (-22us) & uncapped (neutral),
// streaming store hints (neutral), L2 evict_last pinning (neutral),
// persistent grid (-4us), 256-bit loads (-36us).

#define V_THRESH 1.0f
#define TIME_C 0.5f
#define REFRAC_SET 2.5f   // TIME + TAU_REFRAC

__global__ void __launch_bounds__(256, 8)
spike_layer_kernel(const float4* __restrict__ impulse,
                   const float4* __restrict__ mem,
                   const float4* __restrict__ mem_acc,
                   const float4* __restrict__ refrac_until,
                   const float4* __restrict__ spikecounts,
                   float4* __restrict__ out,   // 6 planes of n4 float4 each
                   int n4) {
    int i = blockIdx.x * blockDim.x + threadIdx.x;
    if (i >= n4) return;

    // Front-batch all 5 loads (MLP = 5, overlap DRAM latency)
    const float4 imp = __ldg(&impulse[i]);
    const float4 m   = __ldg(&mem[i]);
    const float4 ma  = __ldg(&mem_acc[i]);
    const float4 ru  = __ldg(&refrac_until[i]);
    const float4 sc  = __ldg(&spikecounts[i]);

    float4 o_spk, o_mem, o_acc, o_ref, o_cnt, o_trn;

    #pragma unroll
    for (int l = 0; l < 4; ++l) {
        const float impv = (&imp.x)[l];
        const float memv = (&m.x)[l];
        const float accv = (&ma.x)[l];
        const float ruv  = (&ru.x)[l];
        const float scv  = (&sc.x)[l];

        // refractory mask on input
        const float masked  = (ruv > TIME_C) ? 0.0f : impv;
        const float new_mem = memv + masked;
        const float new_acc = accv + masked;

        // linear activation: spikes in {0, V_THRESH}
        const bool  fired  = (new_mem >= V_THRESH);
        const float spikes = fired ? V_THRESH : 0.0f;

        // reset by subtraction (spikes<0 branch is unreachable: spikes>=0)
        const float mem_out = fired ? (new_mem - V_THRESH) : new_mem;
        const float ref_out = fired ? REFRAC_SET : ruv;
        const float cnt_out = scv + (fired ? 1.0f : 0.0f);
        const float trn_out = spikes * TIME_C;

        (&o_spk.x)[l] = spikes;
        (&o_mem.x)[l] = mem_out;
        (&o_acc.x)[l] = new_acc;
        (&o_ref.x)[l] = ref_out;
        (&o_cnt.x)[l] = cnt_out;
        (&o_trn.x)[l] = trn_out;
    }

    // 6 output planes, each n4 float4 apart
    out[0 * (size_t)n4 + i] = o_spk;
    out[1 * (size_t)n4 + i] = o_mem;
    out[2 * (size_t)n4 + i] = o_acc;
    out[3 * (size_t)n4 + i] = o_ref;
    out[4 * (size_t)n4 + i] = o_cnt;
    out[5 * (size_t)n4 + i] = o_trn;
}

extern "C" void kernel_launch(void* const* d_in, const int* in_sizes, int n_in,
                              void* d_out, int out_size) {
    const float4* impulse      = (const float4*)d_in[0];
    const float4* mem          = (const float4*)d_in[1];
    const float4* mem_acc      = (const float4*)d_in[2];
    const float4* refrac_until = (const float4*)d_in[3];
    const float4* spikecounts  = (const float4*)d_in[4];
    float4* out = (float4*)d_out;

    const int n  = in_sizes[0];       // 12,845,056 (divisible by 4)
    const int n4 = n / 4;             // 3,211,264

    const int threads = 256;
    const int blocks  = (n4 + threads - 1) / threads;
    spike_layer_kernel<<<blocks, threads>>>(impulse, mem, mem_acc,
                                            refrac_until, spikecounts,
                                            out, n4);
}